// round 12
// baseline (speedup 1.0000x reference)
#include <cuda_runtime.h>

#define T_STEPS 1024
#define N_AGENTS 128
#define R_RUNS 128
#define PF 3
#define NPHASE 1089   // 3*363 >= 1087; extra phases fully store-gated

typedef unsigned long long u64;

__device__ __forceinline__ float tanh_approx(float x) {
    float r;
    asm("tanh.approx.f32 %0, %1;" : "=f"(r) : "f"(x));
    return r;
}
__device__ __forceinline__ float ex2_approx(float x) {
    float r;
    asm("ex2.approx.f32 %0, %1;" : "=f"(r) : "f"(x));
    return r;
}
__device__ __forceinline__ float rcp_approx(float x) {
    float r;
    asm("rcp.approx.f32 %0, %1;" : "=f"(r) : "f"(x));
    return r;
}
__device__ __forceinline__ u64 pk(float lo, float hi) {
    u64 r;
    asm("mov.b64 %0, {%1, %2};" : "=l"(r) : "f"(lo), "f"(hi));
    return r;
}
__device__ __forceinline__ void upk(float& lo, float& hi, u64 v) {
    asm("mov.b64 {%0, %1}, %2;" : "=f"(lo), "=f"(hi) : "l"(v));
}
__device__ __forceinline__ u64 fma2(u64 a, u64 b, u64 c) {
    u64 d;
    asm("fma.rn.f32x2 %0, %1, %2, %3;" : "=l"(d) : "l"(a), "l"(b), "l"(c));
    return d;
}
// predicated vector store: no BSSY/BSYNC
__device__ __forceinline__ void st2_pred(float* p, unsigned t, float v0, float v1) {
    asm volatile("{\n\t.reg .pred q;\n\tsetp.lt.u32 q, %0, 1024;\n\t@q st.global.v2.f32 [%1], {%2, %3};\n\t}"
                 :: "r"(t), "l"(p), "f"(v0), "f"(v1) : "memory");
}
__device__ __forceinline__ void st2_pred_off(float* p, unsigned t, float v0, float v1) {
    asm volatile("{\n\t.reg .pred q;\n\tsetp.lt.u32 q, %0, 1024;\n\t@q st.global.v2.f32 [%1+-504], {%2, %3};\n\t}"
                 :: "r"(t), "l"(p), "f"(v0), "f"(v1) : "memory");
}

#define L1Y(Y, Q, A_, B_) do {                                                 \
    u64 aa_ = pk((A_), (A_)), bb_ = pk((B_), (B_));                            \
    _Pragma("unroll")                                                          \
    for (int j2 = 0; j2 < 5; ++j2) {                                           \
        u64 y2_ = fma2(U3p[j2], bb_, fma2(U2p[j2], aa_, (Q)[j2]));             \
        upk((Y)[2*j2], (Y)[2*j2+1], y2_);                                      \
    }                                                                          \
} while (0)

// Hybrid activation: units 0-5 (pairs 0-2) sigmoid form (y prescaled by S),
// units 6-9 (pairs 3-4) tanh. Produces packed H2[5].
#define ACT(H2, Y) do {                                                        \
    float e_[6], d_[6];                                                        \
    _Pragma("unroll")                                                          \
    for (int j = 0; j < 6; ++j) e_[j] = ex2_approx((Y)[j]);                    \
    float th6_ = tanh_approx((Y)[6]);                                          \
    float th7_ = tanh_approx((Y)[7]);                                          \
    float th8_ = tanh_approx((Y)[8]);                                          \
    float th9_ = tanh_approx((Y)[9]);                                          \
    _Pragma("unroll")                                                          \
    for (int j = 0; j < 6; ++j) d_[j] = e_[j] + 1.0f;                          \
    _Pragma("unroll")                                                          \
    for (int j2 = 0; j2 < 3; ++j2) {                                           \
        float m_ = d_[2*j2] * d_[2*j2+1];                                      \
        float r_ = rcp_approx(m_);                                             \
        (H2)[j2] = pk(d_[2*j2+1] * r_, d_[2*j2] * r_);                         \
    }                                                                          \
    (H2)[3] = pk(th6_, th7_);                                                  \
    (H2)[4] = pk(th8_, th9_);                                                  \
} while (0)

// layer-2 from packed hidden H2[5]; o1/o2 first (feed dependencies), o0 last
#define L2(H2, O0, O1, O2) do {                                                \
    u64 a1a_ = fma2(V1p[0], (H2)[0], C21p);                                    \
    u64 a1b_ = fma2(V1p[1], (H2)[1], fma2(V1p[2], (H2)[2], (u64)0));           \
    u64 a2a_ = fma2(V2p[0], (H2)[0], C22p);                                    \
    u64 a2b_ = fma2(V2p[1], (H2)[1], fma2(V2p[2], (H2)[2], (u64)0));           \
    a1a_ = fma2(V1p[3], (H2)[3], a1a_);                                        \
    a1b_ = fma2(V1p[4], (H2)[4], a1b_);                                        \
    a2a_ = fma2(V2p[3], (H2)[3], a2a_);                                        \
    a2b_ = fma2(V2p[4], (H2)[4], a2b_);                                        \
    float l1a_, h1a_, l1b_, h1b_, l2a_, h2a_, l2b_, h2b_;                      \
    upk(l1a_, h1a_, a1a_); upk(l1b_, h1b_, a1b_);                              \
    upk(l2a_, h2a_, a2a_); upk(l2b_, h2b_, a2b_);                              \
    (O1) = (l1a_ + h1a_) + (l1b_ + h1b_);                                      \
    (O2) = (l2a_ + h2a_) + (l2b_ + h2b_);                                      \
    u64 a0_ = fma2(V0p[0], (H2)[0], C20p);                                     \
    _Pragma("unroll")                                                          \
    for (int j2 = 1; j2 < 5; ++j2) a0_ = fma2(V0p[j2], (H2)[j2], a0_);         \
    float l0_, h0_;                                                            \
    upk(l0_, h0_, a0_);                                                        \
    (O0) = l0_ + h0_;                                                          \
} while (0)

#define MAKE_Q(Q, X0, X1) do {                                                 \
    u64 xx0_ = pk((X0), (X0)), xx1_ = pk((X1), (X1));                          \
    _Pragma("unroll")                                                          \
    for (int j2 = 0; j2 < 5; ++j2)                                             \
        (Q)[j2] = fma2(U1p[j2], xx1_, fma2(U0p[j2], xx0_, C1p[j2]));           \
} while (0)

// One phase with static queue slot I (0..2).
#define PHASE_ITER(I) do {                                                     \
    const float aUp = __shfl_up_sync(0xffffffffu, o2B1, 1);                    \
    const float aA0 = (k == 0) ? 0.f : aUp;                                    \
    const float bA0 = (t0 >= 1) ? o1B0 : 0.f;                                  \
    const float aA1 = o2B0;                                                    \
    const float bA1 = (t0 >= 2) ? o1B1 : 0.f;                                  \
    const float4 h0 = xq0[I], h1 = xq1[I];                                     \
    const float4 n0 = *(const float4*)pf0;                                     \
    const float4 n1 = *(const float4*)pf1;                                     \
    xq0[I] = n0; xq1[I] = n1;                                                  \
    pf0 = ((unsigned)(t0 + PF) <= (T_STEPS - 2)) ? (pf0 + N_AGENTS * 2) : pf0; \
    pf1 = ((unsigned)(t0 - 1 + PF) <= (T_STEPS - 2)) ? (pf1 + N_AGENTS * 2) : pf1; \
    /* A-stage */                                                              \
    u64 qa0[5], qa1[5];                                                        \
    MAKE_Q(qa0, h0.x, h0.y);                                                   \
    MAKE_Q(qa1, h1.x, h1.y);                                                   \
    float yA0[10], yA1[10];                                                    \
    L1Y(yA0, qa0, aA0, bA0);                                                   \
    L1Y(yA1, qa1, aA1, bA1);                                                   \
    u64 hA0[5], hA1[5];                                                        \
    ACT(hA0, yA0);                                                             \
    ACT(hA1, yA1);                                                             \
    u64 qb0[5], qb1[5];                                                        \
    MAKE_Q(qb0, h0.z, h0.w);                                                   \
    MAKE_Q(qb1, h1.z, h1.w);                                                   \
    float o0A0, o1A0, o2A0, o0A1, o1A1, o2A1;                                  \
    L2(hA0, o0A0, o1A0, o2A0);                                                 \
    L2(hA1, o0A1, o1A1, o2A1);                                                 \
    const float bDn = __shfl_down_sync(0xffffffffu, o1A0, 1);                  \
    const float bB0 = (t0 >= 1) ? o1A1 : 0.f;                                  \
    const float bB1 = (t0 >= 2) ? ((k == 31) ? 0.f : bDn) : 0.f;               \
    /* B-stage */                                                              \
    float yB0[10], yB1[10];                                                    \
    L1Y(yB0, qb0, o2A0, bB0);                                                  \
    L1Y(yB1, qb1, o2A1, bB1);                                                  \
    u64 hB0[5], hB1[5];                                                        \
    ACT(hB0, yB0);                                                             \
    ACT(hB1, yB1);                                                             \
    float o0B0, n_o1B0, n_o2B0, o0B1, n_o1B1, n_o2B1;                          \
    L2(hB0, o0B0, n_o1B0, n_o2B0);                                             \
    L2(hB1, o0B1, n_o1B1, n_o2B1);                                             \
    o1B0 = n_o1B0; o2B0 = n_o2B0;                                              \
    o1B1 = n_o1B1; o2B1 = n_o2B1;                                              \
    st2_pred(optr, (unsigned)t0, o0A0, o0B0);                                  \
    st2_pred_off(optr, (unsigned)(t0 - 1), o0A1, o0B1);                        \
    optr += N_AGENTS;                                                          \
    ++t0;                                                                      \
} while (0)

__global__ __launch_bounds__(32, 1)
void com2net_hyb(const float* __restrict__ runs,
                 const float* __restrict__ W1,
                 const float* __restrict__ b1,
                 const float* __restrict__ W2,
                 const float* __restrict__ b2,
                 float* __restrict__ out)
{
    const int k = threadIdx.x;   // lane owns pairs 2k (agents 4k,4k+1 @ t0) and 2k+1 (agents 4k+2,4k+3 @ t0-1)
    const int r = blockIdx.x;

    // ---- pack weights; hidden units 0-5 sigmoid-form (prescale S), 6-9 tanh ----
    const float S = -2.8853900817779268f;   // -2*log2(e): tanh(z) = 2/(1+2^(S z)) - 1
    u64 U0p[5], U1p[5], U2p[5], U3p[5], C1p[5];
#pragma unroll
    for (int j2 = 0; j2 < 5; ++j2) {
        int j = 2 * j2;
        float sc = (j2 < 3) ? S : 1.0f;
        U0p[j2] = pk(W1[j*4+0] * sc, W1[(j+1)*4+0] * sc);
        U1p[j2] = pk(W1[j*4+1] * sc, W1[(j+1)*4+1] * sc);
        U2p[j2] = pk(W1[j*4+2] * sc, W1[(j+1)*4+2] * sc);
        U3p[j2] = pk(W1[j*4+3] * sc, W1[(j+1)*4+3] * sc);
        C1p[j2] = pk(b1[j] * sc,     b1[j+1] * sc);
    }
    u64 V0p[5], V1p[5], V2p[5], C20p, C21p, C22p;
    {
        // bias correction: b2 - sum over SIGMOID units of W2[:,j]
        float s0 = 0.f, s1 = 0.f, s2 = 0.f;
#pragma unroll
        for (int j = 0; j < 6; ++j) {
            s0 += W2[0*10 + j]; s1 += W2[1*10 + j]; s2 += W2[2*10 + j];
        }
#pragma unroll
        for (int j2 = 0; j2 < 5; ++j2) {
            int j = 2 * j2;
            float sc = (j2 < 3) ? 2.0f : 1.0f;
            V0p[j2] = pk(sc * W2[0*10+j], sc * W2[0*10+j+1]);
            V1p[j2] = pk(sc * W2[1*10+j], sc * W2[1*10+j+1]);
            V2p[j2] = pk(sc * W2[2*10+j], sc * W2[2*10+j+1]);
        }
        C20p = pk(b2[0] - s0, 0.f);
        C21p = pk(b2[1] - s1, 0.f);
        C22p = pk(b2[2] - s2, 0.f);
    }

    const float* xb0 = runs + (size_t)r * T_STEPS * N_AGENTS * 2 + (size_t)k * 8;
    const float* xb1 = xb0 + 4;

    float4 xq0[PF], xq1[PF];
#pragma unroll
    for (int d = 0; d < PF; ++d) {
        int t0c = d - 2 * k;       t0c = max(0, min(T_STEPS - 1, t0c));
        int t1c = d - 2 * k - 1;   t1c = max(0, min(T_STEPS - 1, t1c));
        xq0[d] = *(const float4*)(xb0 + (size_t)t0c * (N_AGENTS * 2));
        xq1[d] = *(const float4*)(xb1 + (size_t)t1c * (N_AGENTS * 2));
    }
    const float* pf0;
    const float* pf1;
    {
        int t0c = PF - 2 * k;       t0c = max(0, min(T_STEPS - 1, t0c));
        int t1c = PF - 2 * k - 1;   t1c = max(0, min(T_STEPS - 1, t1c));
        pf0 = xb0 + (size_t)t0c * (N_AGENTS * 2);
        pf1 = xb1 + (size_t)t1c * (N_AGENTS * 2);
    }

    float* optr = out + (size_t)r * T_STEPS * N_AGENTS + (size_t)4 * k
                      + (long long)(-2 * k) * N_AGENTS;
    int t0 = -2 * k;

    float o1B0 = 0.f, o2B0 = 0.f, o1B1 = 0.f, o2B1 = 0.f;

#pragma unroll 1
    for (int pb = 0; pb < NPHASE; pb += 3) {
        PHASE_ITER(0);
        PHASE_ITER(1);
        PHASE_ITER(2);
    }
}

extern "C" void kernel_launch(void* const* d_in, const int* in_sizes, int n_in,
                              void* d_out, int out_size)
{
    const float* runs = (const float*)d_in[0];
    const float* W1   = (const float*)d_in[1];
    const float* b1   = (const float*)d_in[2];
    const float* W2   = (const float*)d_in[3];
    const float* b2   = (const float*)d_in[4];
    float* out = (float*)d_out;
    com2net_hyb<<<R_RUNS, 32>>>(runs, W1, b1, W2, b2, out);
}

// round 13
// speedup vs baseline: 1.1789x; 1.1789x over previous
#include <cuda_runtime.h>

#define T_STEPS 1024
#define N_AGENTS 128
#define R_RUNS 128
#define PF 3
#define NPHASE 1089   // 3*363 >= 1087; extra phases fully store-gated

typedef unsigned long long u64;

__device__ __forceinline__ float tanh_approx(float x) {
    float r;
    asm("tanh.approx.f32 %0, %1;" : "=f"(r) : "f"(x));
    return r;
}
__device__ __forceinline__ u64 pk(float lo, float hi) {
    u64 r;
    asm("mov.b64 %0, {%1, %2};" : "=l"(r) : "f"(lo), "f"(hi));
    return r;
}
__device__ __forceinline__ void upk(float& lo, float& hi, u64 v) {
    asm("mov.b64 {%0, %1}, %2;" : "=f"(lo), "=f"(hi) : "l"(v));
}
__device__ __forceinline__ u64 fma2(u64 a, u64 b, u64 c) {
    u64 d;
    asm("fma.rn.f32x2 %0, %1, %2, %3;" : "=l"(d) : "l"(a), "l"(b), "l"(c));
    return d;
}
// predicated vector store: no BSSY/BSYNC
__device__ __forceinline__ void st2_pred(float* p, unsigned t, float v0, float v1) {
    asm volatile("{\n\t.reg .pred q;\n\tsetp.lt.u32 q, %0, 1024;\n\t@q st.global.v2.f32 [%1], {%2, %3};\n\t}"
                 :: "r"(t), "l"(p), "f"(v0), "f"(v1) : "memory");
}
__device__ __forceinline__ void st2_pred_off(float* p, unsigned t, float v0, float v1) {
    asm volatile("{\n\t.reg .pred q;\n\tsetp.lt.u32 q, %0, 1024;\n\t@q st.global.v2.f32 [%1+-504], {%2, %3};\n\t}"
                 :: "r"(t), "l"(p), "f"(v0), "f"(v1) : "memory");
}

// b-outermost: use when the B-operand is the late dependency... wait, outermost = closest to tanh.
// L1Y_BOUT: y = fma2(U3*b, fma2(U2*a, Q)) -> only ONE fma2 between b and tanh (b late-friendly).
#define L1Y_BOUT(Y, Q, A_, B_) do {                                            \
    u64 aa_ = pk((A_), (A_)), bb_ = pk((B_), (B_));                            \
    _Pragma("unroll")                                                          \
    for (int j2 = 0; j2 < 5; ++j2) {                                           \
        u64 y2_ = fma2(U3p[j2], bb_, fma2(U2p[j2], aa_, (Q)[j2]));             \
        upk((Y)[2*j2], (Y)[2*j2+1], y2_);                                      \
    }                                                                          \
} while (0)
// L1Y_AOUT: y = fma2(U2*a, fma2(U3*b, Q)) -> one fma2 between a and tanh (a late-friendly).
#define L1Y_AOUT(Y, Q, A_, B_) do {                                            \
    u64 aa_ = pk((A_), (A_)), bb_ = pk((B_), (B_));                            \
    _Pragma("unroll")                                                          \
    for (int j2 = 0; j2 < 5; ++j2) {                                           \
        u64 y2_ = fma2(U2p[j2], aa_, fma2(U3p[j2], bb_, (Q)[j2]));             \
        upk((Y)[2*j2], (Y)[2*j2+1], y2_);                                      \
    }                                                                          \
} while (0)

#define L2(H, O0, O1, O2) do {                                                 \
    u64 s_[5];                                                                 \
    _Pragma("unroll")                                                          \
    for (int j2 = 0; j2 < 5; ++j2) s_[j2] = pk((H)[2*j2], (H)[2*j2+1]);        \
    u64 a0_ = fma2(V0p[0], s_[0], C20p);                                       \
    u64 a1_ = fma2(V1p[0], s_[0], C21p);                                       \
    u64 a2_ = fma2(V2p[0], s_[0], C22p);                                       \
    _Pragma("unroll")                                                          \
    for (int j2 = 1; j2 < 5; ++j2) {                                           \
        a0_ = fma2(V0p[j2], s_[j2], a0_);                                      \
        a1_ = fma2(V1p[j2], s_[j2], a1_);                                      \
        a2_ = fma2(V2p[j2], s_[j2], a2_);                                      \
    }                                                                          \
    float l0_, h0_, l1_, h1_, l2_, h2_;                                        \
    upk(l0_, h0_, a0_); upk(l1_, h1_, a1_); upk(l2_, h2_, a2_);                \
    (O0) = l0_ + h0_; (O1) = l1_ + h1_; (O2) = l2_ + h2_;                      \
} while (0)

#define MAKE_Q(Q, X0, X1) do {                                                 \
    u64 xx0_ = pk((X0), (X0)), xx1_ = pk((X1), (X1));                          \
    _Pragma("unroll")                                                          \
    for (int j2 = 0; j2 < 5; ++j2)                                             \
        (Q)[j2] = fma2(U1p[j2], xx1_, fma2(U0p[j2], xx0_, C1p[j2]));           \
} while (0)

#define TANH10(H, Y) do {                                                      \
    _Pragma("unroll")                                                          \
    for (int j = 0; j < 10; ++j) (H)[j] = tanh_approx((Y)[j]);                 \
} while (0)

// One phase, static queue slot I.
// Carried across phases: aIn (pre-shuffled + gated a-input for A0),
// o1B0, o2B0, o1B1 (B outputs of prev phase).
// Order: A0 -> shfl_down -> A1 -> B1 -> shfl_up -> B0.
#define PHASE_ITER(I) do {                                                     \
    const float4 h0 = xq0[I], h1 = xq1[I];                                     \
    const float4 n0 = *(const float4*)pf0;                                     \
    const float4 n1 = *(const float4*)pf1;                                     \
    xq0[I] = n0; xq1[I] = n1;                                                  \
    pf0 = ((unsigned)(t0 + PF) <= (T_STEPS - 2)) ? (pf0 + N_AGENTS * 2) : pf0; \
    pf1 = ((unsigned)(t0 - 1 + PF) <= (T_STEPS - 2)) ? (pf1 + N_AGENTS * 2) : pf1; \
    u64 qa0[5], qa1[5], qb0[5], qb1[5];                                        \
    MAKE_Q(qa0, h0.x, h0.y);                                                   \
    MAKE_Q(qa1, h1.x, h1.y);                                                   \
    MAKE_Q(qb0, h0.z, h0.w);                                                   \
    MAKE_Q(qb1, h1.z, h1.w);                                                   \
    /* ---- A0: late dep = aIn (shfl from prev phase) -> a-outermost ---- */   \
    const float bA0 = (t0 >= 1) ? o1B0 : 0.f;                                  \
    float yA0[10], hA0[10];                                                    \
    L1Y_AOUT(yA0, qa0, aIn, bA0);                                              \
    TANH10(hA0, yA0);                                                          \
    float o0A0, o1A0, o2A0;                                                    \
    L2(hA0, o0A0, o1A0, o2A0);                                                 \
    const float bDn = __shfl_down_sync(0xffffffffu, o1A0, 1);                  \
    /* ---- A1: both deps old ---- */                                          \
    const float bA1 = (t0 >= 2) ? o1B1 : 0.f;                                  \
    float yA1[10], hA1[10];                                                    \
    L1Y_BOUT(yA1, qa1, o2B0, bA1);                                             \
    TANH10(hA1, yA1);                                                          \
    float o0A1, o1A1, o2A1;                                                    \
    L2(hA1, o0A1, o1A1, o2A1);                                                 \
    /* ---- B1: late dep = o2A1 (a) -> a-outermost; bDn already arrived ---- */\
    const float bB1 = (t0 >= 2) ? ((k == 31) ? 0.f : bDn) : 0.f;               \
    float yB1[10], hB1[10];                                                    \
    L1Y_AOUT(yB1, qb1, o2A1, bB1);                                             \
    TANH10(hB1, yB1);                                                          \
    float o0B1, n_o1B1, n_o2B1;                                                \
    L2(hB1, o0B1, n_o1B1, n_o2B1);                                             \
    /* shfl_up for NEXT phase issued here; latency hides under B0 tanh */      \
    const float aUp = __shfl_up_sync(0xffffffffu, n_o2B1, 1);                  \
    /* ---- B0: late dep = o1A1 (b) -> b-outermost ---- */                     \
    const float bB0 = (t0 >= 1) ? o1A1 : 0.f;                                  \
    float yB0[10], hB0[10];                                                    \
    L1Y_BOUT(yB0, qb0, o2A0, bB0);                                             \
    TANH10(hB0, yB0);                                                          \
    float o0B0, n_o1B0, n_o2B0;                                                \
    L2(hB0, o0B0, n_o1B0, n_o2B0);                                             \
    o1B0 = n_o1B0; o2B0 = n_o2B0; o1B1 = n_o1B1;                               \
    aIn = (k == 0) ? 0.f : aUp;                                                \
    st2_pred(optr, (unsigned)t0, o0A0, o0B0);                                  \
    st2_pred_off(optr, (unsigned)(t0 - 1), o0A1, o0B1);                        \
    optr += N_AGENTS;                                                          \
    ++t0;                                                                      \
} while (0)

__global__ __launch_bounds__(32, 1)
void com2net_dag(const float* __restrict__ runs,
                 const float* __restrict__ W1,
                 const float* __restrict__ b1,
                 const float* __restrict__ W2,
                 const float* __restrict__ b2,
                 float* __restrict__ out)
{
    const int k = threadIdx.x;   // lane owns pairs 2k (agents 4k,4k+1 @ t0) and 2k+1 (agents 4k+2,4k+3 @ t0-1)
    const int r = blockIdx.x;

    // ---- pack weights over hidden-unit pairs ----
    u64 U0p[5], U1p[5], U2p[5], U3p[5], C1p[5];
#pragma unroll
    for (int j2 = 0; j2 < 5; ++j2) {
        int j = 2 * j2;
        U0p[j2] = pk(W1[j*4+0], W1[(j+1)*4+0]);
        U1p[j2] = pk(W1[j*4+1], W1[(j+1)*4+1]);
        U2p[j2] = pk(W1[j*4+2], W1[(j+1)*4+2]);
        U3p[j2] = pk(W1[j*4+3], W1[(j+1)*4+3]);
        C1p[j2] = pk(b1[j],     b1[j+1]);
    }
    u64 V0p[5], V1p[5], V2p[5], C20p, C21p, C22p;
#pragma unroll
    for (int j2 = 0; j2 < 5; ++j2) {
        int j = 2 * j2;
        V0p[j2] = pk(W2[0*10+j], W2[0*10+j+1]);
        V1p[j2] = pk(W2[1*10+j], W2[1*10+j+1]);
        V2p[j2] = pk(W2[2*10+j], W2[2*10+j+1]);
    }
    C20p = pk(b2[0], 0.f);
    C21p = pk(b2[1], 0.f);
    C22p = pk(b2[2], 0.f);

    const float* xb0 = runs + (size_t)r * T_STEPS * N_AGENTS * 2 + (size_t)k * 8;
    const float* xb1 = xb0 + 4;

    float4 xq0[PF], xq1[PF];
#pragma unroll
    for (int d = 0; d < PF; ++d) {
        int t0c = d - 2 * k;       t0c = max(0, min(T_STEPS - 1, t0c));
        int t1c = d - 2 * k - 1;   t1c = max(0, min(T_STEPS - 1, t1c));
        xq0[d] = *(const float4*)(xb0 + (size_t)t0c * (N_AGENTS * 2));
        xq1[d] = *(const float4*)(xb1 + (size_t)t1c * (N_AGENTS * 2));
    }
    const float* pf0;
    const float* pf1;
    {
        int t0c = PF - 2 * k;       t0c = max(0, min(T_STEPS - 1, t0c));
        int t1c = PF - 2 * k - 1;   t1c = max(0, min(T_STEPS - 1, t1c));
        pf0 = xb0 + (size_t)t0c * (N_AGENTS * 2);
        pf1 = xb1 + (size_t)t1c * (N_AGENTS * 2);
    }

    float* optr = out + (size_t)r * T_STEPS * N_AGENTS + (size_t)4 * k
                      + (long long)(-2 * k) * N_AGENTS;
    int t0 = -2 * k;

    float o1B0 = 0.f, o2B0 = 0.f, o1B1 = 0.f;
    float aIn = 0.f;   // gated shfl_up(o2B1) carried from prev phase (phase 0: all zero)

#pragma unroll 1
    for (int pb = 0; pb < NPHASE; pb += 3) {
        PHASE_ITER(0);
        PHASE_ITER(1);
        PHASE_ITER(2);
    }
}

extern "C" void kernel_launch(void* const* d_in, const int* in_sizes, int n_in,
                              void* d_out, int out_size)
{
    const float* runs = (const float*)d_in[0];
    const float* W1   = (const float*)d_in[1];
    const float* b1   = (const float*)d_in[2];
    const float* W2   = (const float*)d_in[3];
    const float* b2   = (const float*)d_in[4];
    float* out = (float*)d_out;
    com2net_dag<<<R_RUNS, 32>>>(runs, W1, b1, W2, b2, out);
}

// round 14
// speedup vs baseline: 1.2550x; 1.0645x over previous
#include <cuda_runtime.h>

#define T_STEPS 1024
#define N_AGENTS 128
#define R_RUNS 128
#define PF 3
#define NPHASE 1089   // 3*363 >= 1087; extra phases fully store-gated

typedef unsigned long long u64;

__device__ __forceinline__ float tanh_approx(float x) {
    float r;
    asm("tanh.approx.f32 %0, %1;" : "=f"(r) : "f"(x));
    return r;
}
__device__ __forceinline__ u64 pk(float lo, float hi) {
    u64 r;
    asm("mov.b64 %0, {%1, %2};" : "=l"(r) : "f"(lo), "f"(hi));
    return r;
}
__device__ __forceinline__ void upk(float& lo, float& hi, u64 v) {
    asm("mov.b64 {%0, %1}, %2;" : "=f"(lo), "=f"(hi) : "l"(v));
}
__device__ __forceinline__ u64 fma2(u64 a, u64 b, u64 c) {
    u64 d;
    asm("fma.rn.f32x2 %0, %1, %2, %3;" : "=l"(d) : "l"(a), "l"(b), "l"(c));
    return d;
}
// predicated vector store: no BSSY/BSYNC
__device__ __forceinline__ void st2_pred(float* p, unsigned t, float v0, float v1) {
    asm volatile("{\n\t.reg .pred q;\n\tsetp.lt.u32 q, %0, 1024;\n\t@q st.global.v2.f32 [%1], {%2, %3};\n\t}"
                 :: "r"(t), "l"(p), "f"(v0), "f"(v1) : "memory");
}
__device__ __forceinline__ void st2_pred_off(float* p, unsigned t, float v0, float v1) {
    asm volatile("{\n\t.reg .pred q;\n\tsetp.lt.u32 q, %0, 1024;\n\t@q st.global.v2.f32 [%1+-504], {%2, %3};\n\t}"
                 :: "r"(t), "l"(p), "f"(v0), "f"(v1) : "memory");
}

#define L1Y(Y, Q, A_, B_) do {                                                 \
    u64 aa_ = pk((A_), (A_)), bb_ = pk((B_), (B_));                            \
    _Pragma("unroll")                                                          \
    for (int j2 = 0; j2 < 5; ++j2) {                                           \
        u64 y2_ = fma2(U3p[j2], bb_, fma2(U2p[j2], aa_, (Q)[j2]));             \
        upk((Y)[2*j2], (Y)[2*j2+1], y2_);                                      \
    }                                                                          \
} while (0)

#define L2(H, O0, O1, O2) do {                                                 \
    u64 s_[5];                                                                 \
    _Pragma("unroll")                                                          \
    for (int j2 = 0; j2 < 5; ++j2) s_[j2] = pk((H)[2*j2], (H)[2*j2+1]);        \
    u64 a0_ = fma2(V0p[0], s_[0], C20p);                                       \
    u64 a1_ = fma2(V1p[0], s_[0], C21p);                                       \
    u64 a2_ = fma2(V2p[0], s_[0], C22p);                                       \
    _Pragma("unroll")                                                          \
    for (int j2 = 1; j2 < 5; ++j2) {                                           \
        a0_ = fma2(V0p[j2], s_[j2], a0_);                                      \
        a1_ = fma2(V1p[j2], s_[j2], a1_);                                      \
        a2_ = fma2(V2p[j2], s_[j2], a2_);                                      \
    }                                                                          \
    float l0_, h0_, l1_, h1_, l2_, h2_;                                        \
    upk(l0_, h0_, a0_); upk(l1_, h1_, a1_); upk(l2_, h2_, a2_);                \
    (O0) = l0_ + h0_; (O1) = l1_ + h1_; (O2) = l2_ + h2_;                      \
} while (0)

#define MAKE_Q(Q, X0, X1) do {                                                 \
    u64 xx0_ = pk((X0), (X0)), xx1_ = pk((X1), (X1));                          \
    _Pragma("unroll")                                                          \
    for (int j2 = 0; j2 < 5; ++j2)                                             \
        (Q)[j2] = fma2(U1p[j2], xx1_, fma2(U0p[j2], xx0_, C1p[j2]));           \
} while (0)

// One phase with static queue slot I (0..2).
// R11 structure exactly; ONLY change: shfl_up(o2B1) hoisted to the phase TAIL
// (issued right after B-stage produces o2B1), carried across phases in aIn.
#define PHASE_ITER(I) do {                                                     \
    const float aA0 = aIn;                                                     \
    const float bA0 = (t0 >= 1) ? o1B0 : 0.f;                                  \
    const float aA1 = o2B0;                                                    \
    const float bA1 = (t0 >= 2) ? o1B1 : 0.f;                                  \
    const float4 h0 = xq0[I], h1 = xq1[I];                                     \
    const float4 n0 = *(const float4*)pf0;                                     \
    const float4 n1 = *(const float4*)pf1;                                     \
    xq0[I] = n0; xq1[I] = n1;                                                  \
    pf0 = ((unsigned)(t0 + PF) <= (T_STEPS - 2)) ? (pf0 + N_AGENTS * 2) : pf0; \
    pf1 = ((unsigned)(t0 - 1 + PF) <= (T_STEPS - 2)) ? (pf1 + N_AGENTS * 2) : pf1; \
    /* A-stage */                                                              \
    u64 qa0[5], qa1[5];                                                        \
    MAKE_Q(qa0, h0.x, h0.y);                                                   \
    MAKE_Q(qa1, h1.x, h1.y);                                                   \
    float yA0[10], yA1[10];                                                    \
    L1Y(yA0, qa0, aA0, bA0);                                                   \
    L1Y(yA1, qa1, aA1, bA1);                                                   \
    float hA0[10], hA1[10];                                                    \
    _Pragma("unroll")                                                          \
    for (int j = 0; j < 10; ++j) {                                             \
        hA0[j] = tanh_approx(yA0[j]);                                          \
        hA1[j] = tanh_approx(yA1[j]);                                          \
    }                                                                          \
    u64 qb0[5], qb1[5];                                                        \
    MAKE_Q(qb0, h0.z, h0.w);                                                   \
    MAKE_Q(qb1, h1.z, h1.w);                                                   \
    float o0A0, o1A0, o2A0, o0A1, o1A1, o2A1;                                  \
    L2(hA0, o0A0, o1A0, o2A0);                                                 \
    L2(hA1, o0A1, o1A1, o2A1);                                                 \
    const float bDn = __shfl_down_sync(0xffffffffu, o1A0, 1);                  \
    const float bB0 = (t0 >= 1) ? o1A1 : 0.f;                                  \
    const float bB1 = (t0 >= 2) ? ((k == 31) ? 0.f : bDn) : 0.f;               \
    /* B-stage */                                                              \
    float yB0[10], yB1[10];                                                    \
    L1Y(yB0, qb0, o2A0, bB0);                                                  \
    L1Y(yB1, qb1, o2A1, bB1);                                                  \
    float hB0[10], hB1[10];                                                    \
    _Pragma("unroll")                                                          \
    for (int j = 0; j < 10; ++j) {                                             \
        hB0[j] = tanh_approx(yB0[j]);                                          \
        hB1[j] = tanh_approx(yB1[j]);                                          \
    }                                                                          \
    float o0B0, n_o1B0, n_o2B0, o0B1, n_o1B1, n_o2B1;                          \
    L2(hB0, o0B0, n_o1B0, n_o2B0);                                             \
    L2(hB1, o0B1, n_o1B1, n_o2B1);                                             \
    o1B0 = n_o1B0; o2B0 = n_o2B0;                                              \
    o1B1 = n_o1B1; o2B1 = n_o2B1;                                              \
    /* hoisted cross-lane exchange for NEXT phase's A0 a-input */              \
    const float aUp = __shfl_up_sync(0xffffffffu, o2B1, 1);                    \
    aIn = (k == 0) ? 0.f : aUp;                                                \
    st2_pred(optr, (unsigned)t0, o0A0, o0B0);                                  \
    st2_pred_off(optr, (unsigned)(t0 - 1), o0A1, o0B1);                        \
    optr += N_AGENTS;                                                          \
    ++t0;                                                                      \
} while (0)

__global__ __launch_bounds__(32, 1)
void com2net_hoist(const float* __restrict__ runs,
                   const float* __restrict__ W1,
                   const float* __restrict__ b1,
                   const float* __restrict__ W2,
                   const float* __restrict__ b2,
                   float* __restrict__ out)
{
    const int k = threadIdx.x;   // lane owns pairs 2k (agents 4k,4k+1 @ t0) and 2k+1 (agents 4k+2,4k+3 @ t0-1)
    const int r = blockIdx.x;

    // ---- pack weights over hidden-unit pairs ----
    u64 U0p[5], U1p[5], U2p[5], U3p[5], C1p[5];
#pragma unroll
    for (int j2 = 0; j2 < 5; ++j2) {
        int j = 2 * j2;
        U0p[j2] = pk(W1[j*4+0], W1[(j+1)*4+0]);
        U1p[j2] = pk(W1[j*4+1], W1[(j+1)*4+1]);
        U2p[j2] = pk(W1[j*4+2], W1[(j+1)*4+2]);
        U3p[j2] = pk(W1[j*4+3], W1[(j+1)*4+3]);
        C1p[j2] = pk(b1[j],     b1[j+1]);
    }
    u64 V0p[5], V1p[5], V2p[5], C20p, C21p, C22p;
#pragma unroll
    for (int j2 = 0; j2 < 5; ++j2) {
        int j = 2 * j2;
        V0p[j2] = pk(W2[0*10+j], W2[0*10+j+1]);
        V1p[j2] = pk(W2[1*10+j], W2[1*10+j+1]);
        V2p[j2] = pk(W2[2*10+j], W2[2*10+j+1]);
    }
    C20p = pk(b2[0], 0.f);
    C21p = pk(b2[1], 0.f);
    C22p = pk(b2[2], 0.f);

    const float* xb0 = runs + (size_t)r * T_STEPS * N_AGENTS * 2 + (size_t)k * 8;
    const float* xb1 = xb0 + 4;

    float4 xq0[PF], xq1[PF];
#pragma unroll
    for (int d = 0; d < PF; ++d) {
        int t0c = d - 2 * k;       t0c = max(0, min(T_STEPS - 1, t0c));
        int t1c = d - 2 * k - 1;   t1c = max(0, min(T_STEPS - 1, t1c));
        xq0[d] = *(const float4*)(xb0 + (size_t)t0c * (N_AGENTS * 2));
        xq1[d] = *(const float4*)(xb1 + (size_t)t1c * (N_AGENTS * 2));
    }
    const float* pf0;
    const float* pf1;
    {
        int t0c = PF - 2 * k;       t0c = max(0, min(T_STEPS - 1, t0c));
        int t1c = PF - 2 * k - 1;   t1c = max(0, min(T_STEPS - 1, t1c));
        pf0 = xb0 + (size_t)t0c * (N_AGENTS * 2);
        pf1 = xb1 + (size_t)t1c * (N_AGENTS * 2);
    }

    float* optr = out + (size_t)r * T_STEPS * N_AGENTS + (size_t)4 * k
                      + (long long)(-2 * k) * N_AGENTS;
    int t0 = -2 * k;

    float o1B0 = 0.f, o2B0 = 0.f, o1B1 = 0.f, o2B1 = 0.f;
    float aIn = 0.f;   // pre-shuffled, gated a-input for A0 (phase 0: zeros)

#pragma unroll 1
    for (int pb = 0; pb < NPHASE; pb += 3) {
        PHASE_ITER(0);
        PHASE_ITER(1);
        PHASE_ITER(2);
    }
}

extern "C" void kernel_launch(void* const* d_in, const int* in_sizes, int n_in,
                              void* d_out, int out_size)
{
    const float* runs = (const float*)d_in[0];
    const float* W1   = (const float*)d_in[1];
    const float* b1   = (const float*)d_in[2];
    const float* W2   = (const float*)d_in[3];
    const float* b2   = (const float*)d_in[4];
    float* out = (float*)d_out;
    com2net_hoist<<<R_RUNS, 32>>>(runs, W1, b1, W2, b2, out);
}